// round 15
// baseline (speedup 1.0000x reference)
#include <cuda_runtime.h>
#include <cuda_fp16.h>
#include <math.h>
#include <stdint.h>

#define BATCH 2
#define SEQ   2048
#define EMB   1024
#define NH    16
#define HD    64
#define MROWS (BATCH*SEQ)   // 4096
#define ACT_N (MROWS*EMB)
#define W_N   (EMB*EMB)

// ---------------------------------------------------------------------------
// Scratch (__device__ globals; no runtime allocation)
// ---------------------------------------------------------------------------
__device__ __half g_a1[3*ACT_N];                  // activations single fp16
__device__ __half g_wh[4*W_N];                    // weights^T single fp16
__device__ __half g_qh[ACT_N];                    // Q post-RoPE single
__device__ __half g_kh[ACT_N];                    // K post-RoPE single
__device__ __half g_vth[ACT_N];                   // V^T [b,h,d,s] single
__device__ __half g_oh[ACT_N];                    // attention out single
__device__ float2 g_rope[SEQ*32];

// exp(s*0.125) == exp2(s * 0.125*log2(e))
#define EXPSCALE 0.18033688011112042f

// ---------------------------------------------------------------------------
// helpers
// ---------------------------------------------------------------------------
__device__ __forceinline__ uint32_t smem_u32(const void* p) {
    uint32_t a;
    asm("{ .reg .u64 t; cvta.to.shared.u64 t, %1; cvt.u32.u64 %0, t; }" : "=r"(a) : "l"(p));
    return a;
}
__device__ __forceinline__ void cpa16(uint32_t dst, const void* src) {
    asm volatile("cp.async.cg.shared.global [%0], [%1], 16;" :: "r"(dst), "l"(src));
}
#define CP_COMMIT() asm volatile("cp.async.commit_group;" ::: "memory")
#define CP_WAIT0()  asm volatile("cp.async.wait_group 0;" ::: "memory")
#define CP_WAIT1()  asm volatile("cp.async.wait_group 1;" ::: "memory")

__device__ __forceinline__ void mma4(float* c, const uint32_t* a, uint32_t b0, uint32_t b1) {
    asm volatile(
        "mma.sync.aligned.m16n8k16.row.col.f32.f16.f16.f32 "
        "{%0,%1,%2,%3}, {%4,%5,%6,%7}, {%8,%9}, {%0,%1,%2,%3};"
        : "+f"(c[0]), "+f"(c[1]), "+f"(c[2]), "+f"(c[3])
        : "r"(a[0]), "r"(a[1]), "r"(a[2]), "r"(a[3]), "r"(b0), "r"(b1));
}
__device__ __forceinline__ void ldsm4(uint32_t* r, uint32_t a) {
    asm volatile("ldmatrix.sync.aligned.m8n8.x4.shared.b16 {%0,%1,%2,%3}, [%4];"
        : "=r"(r[0]), "=r"(r[1]), "=r"(r[2]), "=r"(r[3]) : "r"(a));
}

// 128B-row swizzle (8 chunks of 16B, xor by row&7) — conflict-free ldmatrix
#define SW128X(row, ch) ((row) * 128 + (((ch) ^ (row)) & 7) * 16)

// ---------------------------------------------------------------------------
// RoPE table
// ---------------------------------------------------------------------------
__global__ void rope_table_kernel(float2* __restrict__ tab) {
    int i = blockIdx.x * 256 + threadIdx.x;
    if (i >= SEQ * 32) return;
    int p = i & 31, s = i >> 5;
    double inv = pow(10000.0, -(double)p * (1.0 / 32.0));
    float ph = (float)((double)s * inv);
    float sn, cs;
    sincosf(ph, &sn, &cs);
    tab[i] = make_float2(cs, sn);
}

// ---------------------------------------------------------------------------
// merged input conversions: fp32 -> single fp16, z = 0,1,2 (query,key,value)
// ---------------------------------------------------------------------------
__global__ void __launch_bounds__(256) conv3(const float* __restrict__ x0,
                                             const float* __restrict__ x1,
                                             const float* __restrict__ x2,
                                             __half* __restrict__ hi) {
    int z = blockIdx.y;
    const float* x = (z == 0) ? x0 : (z == 1) ? x1 : x2;
    size_t i = ((size_t)blockIdx.x * 256 + threadIdx.x) * 4;
    float4 v = *(const float4*)(x + i);
    size_t o = (size_t)z * ACT_N + i;
    *(__half2*)(hi + o)     = __halves2half2(__float2half_rn(v.x), __float2half_rn(v.y));
    *(__half2*)(hi + o + 2) = __halves2half2(__float2half_rn(v.z), __float2half_rn(v.w));
}

// merged W[K,N] fp32 -> Wt[N,K] single fp16, z = 0..3 (Wq,Wk,Wv,Wo)
__global__ void __launch_bounds__(256) convT4(const float* __restrict__ W0,
                                              const float* __restrict__ W1,
                                              const float* __restrict__ W2,
                                              const float* __restrict__ W3,
                                              __half* __restrict__ hi) {
    __shared__ float t[32][33];
    int z = blockIdx.z;
    const float* W = (z == 0) ? W0 : (z == 1) ? W1 : (z == 2) ? W2 : W3;
    int tx = threadIdx.x & 31;
    int ty = threadIdx.x >> 5;
    int bk = blockIdx.y * 32, bn = blockIdx.x * 32;
#pragma unroll
    for (int r = ty; r < 32; r += 8)
        t[r][tx] = W[(size_t)(bk + r) * EMB + bn + tx];
    __syncthreads();
#pragma unroll
    for (int r = ty; r < 32; r += 8) {
        size_t o = (size_t)z * W_N + (size_t)(bn + r) * EMB + bk + tx;
        hi[o] = __float2half_rn(t[tx][r]);
    }
}

// ---------------------------------------------------------------------------
// Projection GEMM: BM=128 BN=128 BK=64; 8 warps (4m x 2n), ldmatrix,
// single-pass fp16. 2-stage cp.async (64KB smem) + __launch_bounds__(256,3)
// -> 3 CTAs/SM (24 warps). 16 k-iters, hoisted addresses.
// epi: 0 = RoPE + single store (Q/K); 1 = transposed single store (V^T);
//      2 = fp32 store (output projection)
// ---------------------------------------------------------------------------
#define PJ_STAGE 32768
#define PJ_SMEM  (2*PJ_STAGE)   // 65536
#define PJ_ITERS 16

__device__ __forceinline__ void gemm_core(
    const __half* __restrict__ Ah, const __half* __restrict__ Bh,
    __half* __restrict__ Ch, float* __restrict__ Cf,
    const float2* __restrict__ rope, int epi, char* sm)
{
    const uint32_t sb = smem_u32(sm);
    const int tid  = threadIdx.x;
    const int lane = tid & 31;
    const int wid  = tid >> 5;
    const int g    = lane >> 2;
    const int c    = lane & 3;
    const int quad = lane >> 3;
    const int lr   = lane & 7;
    const int m0 = blockIdx.y * 128;
    const int n0 = blockIdx.x * 128;
    const int wm = (wid & 3) * 32;
    const int wn = (wid >> 2) * 64;

    const int a_row = (quad & 1) * 8 + lr;
    const int a_chi = quad >> 1;
    const int b_row = (quad >> 1) * 8 + lr;
    const int b_chi = quad & 1;

    // hoisted staging addresses: t=0..3 -> A rows, t=4..7 -> B rows
    const __half* Abase = Ah + (size_t)m0 * EMB;
    const __half* Bbase = Bh + (size_t)n0 * EMB;
    uint32_t soff[8], goff[8];
#pragma unroll
    for (int t = 0; t < 8; t++) {
        int idx = t * 256 + tid;
        int buf = idx >> 10;           // 0:A 1:B
        int rem = idx & 1023;
        int row = rem >> 3;
        int j   = rem & 7;
        soff[t] = buf * 16384 + SW128X(row, j);
        goff[t] = row * EMB + j * 8;
    }

    float acc[2][8][4];
#pragma unroll
    for (int i = 0; i < 2; i++)
#pragma unroll
        for (int j = 0; j < 8; j++)
#pragma unroll
            for (int q = 0; q < 4; q++) acc[i][j][q] = 0.f;

    auto stage = [&](int kt, int s) {
        uint32_t base = sb + s * PJ_STAGE;
        uint32_t kadd = kt * 64;
#pragma unroll
        for (int t = 0; t < 4; t++)
            cpa16(base + soff[t], Abase + goff[t] + kadd);
#pragma unroll
        for (int t = 4; t < 8; t++)
            cpa16(base + soff[t], Bbase + goff[t] + kadd);
    };

    stage(0, 0); CP_COMMIT();

#pragma unroll 1
    for (int kt = 0; kt < PJ_ITERS; kt++) {
        const int s = kt & 1;
        CP_WAIT0();
        __syncthreads();               // stage kt visible; all warps done reading s^1
        if (kt + 1 < PJ_ITERS) {
            stage(kt + 1, s ^ 1);      // loads proceed under compute below
            CP_COMMIT();
        }

        const uint32_t base = sb + s * PJ_STAGE;
#pragma unroll
        for (int kk = 0; kk < 4; kk++) {
            uint32_t aH[2][4];
#pragma unroll
            for (int mf = 0; mf < 2; mf++) {
                int row = wm + mf * 16 + a_row;
                int ch  = kk * 2 + a_chi;
                ldsm4(aH[mf], base + SW128X(row, ch));
            }
#pragma unroll
            for (int ngp = 0; ngp < 2; ngp++) {
                int ch = kk * 2 + b_chi;
                uint32_t bv0[4], bv1[4];
                ldsm4(bv0, base + 16384 + SW128X(wn + (ngp * 2 + 0) * 16 + b_row, ch));
                ldsm4(bv1, base + 16384 + SW128X(wn + (ngp * 2 + 1) * 16 + b_row, ch));
#pragma unroll
                for (int t = 0; t < 2; t++)
#pragma unroll
                    for (int mf = 0; mf < 2; mf++) {
                        mma4(acc[mf][(ngp * 2 + 0) * 2 + t], aH[mf], bv0[t * 2], bv0[t * 2 + 1]);
                        mma4(acc[mf][(ngp * 2 + 1) * 2 + t], aH[mf], bv1[t * 2], bv1[t * 2 + 1]);
                    }
            }
        }
    }

    // ---- epilogue ----
#pragma unroll
    for (int mf = 0; mf < 2; mf++) {
#pragma unroll
        for (int rr = 0; rr < 2; rr++) {
            int row = m0 + wm + mf * 16 + g + rr * 8;
            if (epi == 0) {
                int ss = row & (SEQ - 1);
#pragma unroll
                for (int ns = 0; ns < 4; ns++) {
                    int p = ns * 8 + 2 * c;
                    float2 r0 = rope[ss * 32 + p];
                    float2 r1 = rope[ss * 32 + p + 1];
                    float x00 = acc[mf][ns][rr * 2 + 0],     x01 = acc[mf][ns][rr * 2 + 1];
                    float x10 = acc[mf][ns + 4][rr * 2 + 0], x11 = acc[mf][ns + 4][rr * 2 + 1];
                    float o00 = x00 * r0.x - x10 * r0.y;
                    float o10 = x10 * r0.x + x00 * r0.y;
                    float o01 = x01 * r1.x - x11 * r1.y;
                    float o11 = x11 * r1.x + x01 * r1.y;
                    size_t col = (size_t)row * EMB + n0 + wn + p;
                    *(__half2*)(Ch + col) =
                        __halves2half2(__float2half_rn(o00), __float2half_rn(o01));
                    *(__half2*)(Ch + col + 32) =
                        __halves2half2(__float2half_rn(o10), __float2half_rn(o11));
                }
            } else if (epi == 1) {
                int bq = row >> 11;
                int sq = row & (SEQ - 1);
#pragma unroll
                for (int ns = 0; ns < 8; ns++) {
                    int col = n0 + wn + ns * 8 + 2 * c;
                    int hh = col >> 6, d = col & 63;
                    size_t dst = ((size_t)(bq * NH + hh) * 64 + d) * SEQ + sq;
                    Ch[dst]       = __float2half_rn(acc[mf][ns][rr * 2]);
                    Ch[dst + SEQ] = __float2half_rn(acc[mf][ns][rr * 2 + 1]);
                }
            } else {
#pragma unroll
                for (int ns = 0; ns < 8; ns++) {
                    size_t col = (size_t)row * EMB + n0 + wn + ns * 8 + 2 * c;
                    *(float2*)(Cf + col) =
                        make_float2(acc[mf][ns][rr * 2], acc[mf][ns][rr * 2 + 1]);
                }
            }
        }
    }
}

__global__ void __launch_bounds__(256, 3)
gemm_qkv(const __half* __restrict__ a1, const __half* __restrict__ wh,
         __half* __restrict__ qh, __half* __restrict__ kh,
         __half* __restrict__ vth, const float2* __restrict__ rope)
{
    extern __shared__ char sm[];
    int z = blockIdx.z;
    const __half* Ah = a1 + (size_t)z * ACT_N;
    const __half* Bh = wh + (size_t)z * W_N;
    __half* Ch = (z == 0) ? qh : (z == 1) ? kh : vth;
    gemm_core(Ah, Bh, Ch, nullptr, rope, (z < 2) ? 0 : 1, sm);
}

__global__ void __launch_bounds__(256, 3)
gemm_one(const __half* __restrict__ Ah, const __half* __restrict__ Bh,
         float* __restrict__ Cf)
{
    extern __shared__ char sm[];
    gemm_core(Ah, Bh, nullptr, Cf, nullptr, 2, sm);
}

// ---------------------------------------------------------------------------
// Flash attention: all-fp16 single-pass MMAs; fp16x2 MUFU softmax;
// hoisted staging addresses; 3 KV stages. (unchanged)
// smem: Q 0..16K; KV stage s at 16384 + s*16384 (K +0, V +8192)
// ---------------------------------------------------------------------------
#define AT_KV 16384
#define AT_STAGE 16384
#define AT_SMEM (16384 + 3*16384)   // 65536

__global__ void __launch_bounds__(256, 2)
attn_kernel(const __half* __restrict__ Qh, const __half* __restrict__ Kh,
            const __half* __restrict__ Vth, __half* __restrict__ Oh)
{
    extern __shared__ char sm[];
    const uint32_t sb = smem_u32(sm);
    const int tid  = threadIdx.x;
    const int lane = tid & 31;
    const int wid  = tid >> 5;
    const int g    = lane >> 2;
    const int c    = lane & 3;
    const int quad = lane >> 3;
    const int lr   = lane & 7;
    const int q0 = blockIdx.x * 128;
    const int h  = blockIdx.y;
    const int b  = blockIdx.z;
    const int bh = b * NH + h;

    const int a_row = (quad & 1) * 8 + lr;
    const int a_chi = quad >> 1;
    const int b_row = (quad >> 1) * 8 + lr;
    const int b_chi = quad & 1;

    __half2 e2h = __half2half2(__float2half_rn(EXPSCALE));
    const uint32_t esc2 = *(uint32_t*)&e2h;

    // hoisted KV staging addresses: t=0,1 -> K rows, t=2,3 -> V rows
    uint32_t soffKV[4], goffKV[4];
#pragma unroll
    for (int t = 0; t < 4; t++) {
        int idx = t * 256 + tid;
        int buf = idx >> 9;            // 0:K 1:V
        int rem = idx & 511;
        int row = rem >> 3;
        int j   = rem & 7;
        soffKV[t] = buf * 8192 + SW128X(row, j);
        goffKV[t] = buf ? ((uint32_t)(bh * 64 + row) * SEQ + j * 8)
                        : ((uint32_t)(b * SEQ + row) * EMB + h * 64 + j * 8);
    }

    auto stage_kv = [&](int kt, int s) {
        uint32_t base = sb + AT_KV + s * AT_STAGE;
        uint32_t kaddK = (uint32_t)kt * EMB;
        cpa16(base + soffKV[0], Kh  + goffKV[0] + kaddK);
        cpa16(base + soffKV[1], Kh  + goffKV[1] + kaddK);
        cpa16(base + soffKV[2], Vth + goffKV[2] + kt);
        cpa16(base + soffKV[3], Vth + goffKV[3] + kt);
    };

    // stage Q (once) + chunks 0,1
#pragma unroll
    for (int t = 0; t < 4; t++) {
        int idx = t * 256 + tid;
        int row = idx >> 3;
        int j   = idx & 7;
        cpa16(sb + SW128X(row, j),
              Qh + (size_t)(b * SEQ + q0 + row) * EMB + h * 64 + j * 8);
    }
    stage_kv(0, 0);
    CP_COMMIT();
    stage_kv(64, 1);
    CP_COMMIT();

    float Of[8][4];
#pragma unroll
    for (int n = 0; n < 8; n++)
#pragma unroll
        for (int q = 0; q < 4; q++) Of[n][q] = 0.f;
    float lA = 0.f, lB = 0.f;

#pragma unroll 1
    for (int ic = 0; ic < SEQ / 64; ic++) {
        const int s = ic - (ic / 3) * 3;
        CP_WAIT1();
        __syncthreads();
        if (ic + 2 < SEQ / 64) {
            int s2 = (ic + 2) - ((ic + 2) / 3) * 3;
            stage_kv((ic + 2) * 64, s2);
        }
        CP_COMMIT();

        const uint32_t kvb = sb + AT_KV + s * AT_STAGE;

        // ---- S = Q K^T (single pass) ----
        float Sf[8][4];
#pragma unroll
        for (int n = 0; n < 8; n++)
#pragma unroll
            for (int q = 0; q < 4; q++) Sf[n][q] = 0.f;

#pragma unroll
        for (int kk = 0; kk < 4; kk++) {
            uint32_t aH[4];
            {
                int row = wid * 16 + a_row;
                int ch  = kk * 2 + a_chi;
                ldsm4(aH, sb + SW128X(row, ch));
            }
#pragma unroll
            for (int ngp = 0; ngp < 2; ngp++) {
                int ch = kk * 2 + b_chi;
                uint32_t bv0[4], bv1[4];
                ldsm4(bv0, kvb + 0 + SW128X((ngp * 2 + 0) * 16 + b_row, ch));
                ldsm4(bv1, kvb + 0 + SW128X((ngp * 2 + 1) * 16 + b_row, ch));
                mma4(Sf[ngp * 4 + 0], aH, bv0[0], bv0[1]);
                mma4(Sf[ngp * 4 + 1], aH, bv0[2], bv0[3]);
                mma4(Sf[ngp * 4 + 2], aH, bv1[0], bv1[1]);
                mma4(Sf[ngp * 4 + 3], aH, bv1[2], bv1[3]);
            }
        }

        // ---- softmax in fp16x2: P = ex2(s * scale) ----
        uint32_t P01[8], P23[8];
        uint32_t sumA2 = 0, sumB2 = 0;
#pragma unroll
        for (int ns = 0; ns < 8; ns++) {
            uint32_t a01, a23;
            asm("cvt.rn.f16x2.f32 %0, %1, %2;" : "=r"(a01) : "f"(Sf[ns][1]), "f"(Sf[ns][0]));
            asm("cvt.rn.f16x2.f32 %0, %1, %2;" : "=r"(a23) : "f"(Sf[ns][3]), "f"(Sf[ns][2]));
            asm("mul.rn.f16x2 %0, %0, %1;" : "+r"(a01) : "r"(esc2));
            asm("mul.rn.f16x2 %0, %0, %1;" : "+r"(a23) : "r"(esc2));
            asm("ex2.approx.f16x2 %0, %0;" : "+r"(a01));
            asm("ex2.approx.f16x2 %0, %0;" : "+r"(a23));
            P01[ns] = a01;
            P23[ns] = a23;
            asm("add.rn.f16x2 %0, %0, %1;" : "+r"(sumA2) : "r"(a01));
            asm("add.rn.f16x2 %0, %0, %1;" : "+r"(sumB2) : "r"(a23));
        }
        {
            float2 fa = __half22float2(*(__half2*)&sumA2);
            float2 fb = __half22float2(*(__half2*)&sumB2);
            lA += fa.x + fa.y;
            lB += fb.x + fb.y;
        }

        // ---- O += P V ----
#pragma unroll
        for (int kk = 0; kk < 4; kk++) {
            uint32_t ah2[4] = {P01[2 * kk], P23[2 * kk], P01[2 * kk + 1], P23[2 * kk + 1]};
#pragma unroll
            for (int ngp = 0; ngp < 2; ngp++) {
                int ch = kk * 2 + b_chi;
                uint32_t vv0[4], vv1[4];
                ldsm4(vv0, kvb + 8192 + SW128X((ngp * 2 + 0) * 16 + b_row, ch));
                ldsm4(vv1, kvb + 8192 + SW128X((ngp * 2 + 1) * 16 + b_row, ch));
                mma4(Of[ngp * 4 + 0], ah2, vv0[0], vv0[1]);
                mma4(Of[ngp * 4 + 1], ah2, vv0[2], vv0[3]);
                mma4(Of[ngp * 4 + 2], ah2, vv1[0], vv1[1]);
                mma4(Of[ngp * 4 + 3], ah2, vv1[2], vv1[3]);
            }
        }
    }

    // ---- epilogue: single cross-lane reduce, normalize, single fp16 store ----
    lA += __shfl_xor_sync(0xffffffffu, lA, 1);
    lA += __shfl_xor_sync(0xffffffffu, lA, 2);
    lB += __shfl_xor_sync(0xffffffffu, lB, 1);
    lB += __shfl_xor_sync(0xffffffffu, lB, 2);
    float iA = 1.0f / lA, iB = 1.0f / lB;
#pragma unroll
    for (int rr = 0; rr < 2; rr++) {
        int row = b * SEQ + q0 + wid * 16 + g + rr * 8;
        float sc = rr ? iB : iA;
#pragma unroll
        for (int nf = 0; nf < 8; nf++) {
            size_t col = (size_t)row * EMB + h * 64 + nf * 8 + 2 * c;
            *(__half2*)(Oh + col) =
                __halves2half2(__float2half_rn(Of[nf][rr * 2] * sc),
                               __float2half_rn(Of[nf][rr * 2 + 1] * sc));
        }
    }
}

// ---------------------------------------------------------------------------
extern "C" void kernel_launch(void* const* d_in, const int* in_sizes, int n_in,
                              void* d_out, int out_size)
{
    const float* query = (const float*)d_in[0];
    const float* key   = (const float*)d_in[1];
    const float* value = (const float*)d_in[2];
    const float* Wq    = (const float*)d_in[3];
    const float* Wk    = (const float*)d_in[4];
    const float* Wv    = (const float*)d_in[5];
    const float* Wo    = (const float*)d_in[6];
    float* out = (float*)d_out;

    __half *a1, *wh, *qh, *kh, *vth, *oh;
    float2* rope;
    cudaGetSymbolAddress((void**)&a1, g_a1);
    cudaGetSymbolAddress((void**)&wh, g_wh);
    cudaGetSymbolAddress((void**)&qh, g_qh);
    cudaGetSymbolAddress((void**)&kh, g_kh);
    cudaGetSymbolAddress((void**)&vth, g_vth);
    cudaGetSymbolAddress((void**)&oh, g_oh);
    cudaGetSymbolAddress((void**)&rope, g_rope);

    cudaFuncSetAttribute(gemm_qkv,    cudaFuncAttributeMaxDynamicSharedMemorySize, PJ_SMEM);
    cudaFuncSetAttribute(gemm_one,    cudaFuncAttributeMaxDynamicSharedMemorySize, PJ_SMEM);
    cudaFuncSetAttribute(attn_kernel, cudaFuncAttributeMaxDynamicSharedMemorySize, AT_SMEM);

    rope_table_kernel<<<SEQ * 32 / 256, 256>>>(rope);

    conv3<<<dim3(ACT_N / 1024, 3), 256>>>(query, key, value, a1);
    convT4<<<dim3(32, 32, 4), 256>>>(Wq, Wk, Wv, Wo, wh);

    gemm_qkv<<<dim3(EMB / 128, MROWS / 128, 3), 256, PJ_SMEM>>>(
        a1, wh, qh, kh, vth, rope);

    attn_kernel<<<dim3(SEQ / 128, NH, BATCH), 256, AT_SMEM>>>(
        qh, kh, vth, oh);

    gemm_one<<<dim3(EMB / 128, MROWS / 128), 256, PJ_SMEM>>>(
        oh, wh + (size_t)3 * W_N, out);
}

// round 16
// speedup vs baseline: 1.3608x; 1.3608x over previous
#include <cuda_runtime.h>
#include <cuda_fp16.h>
#include <math.h>
#include <stdint.h>

#define BATCH 2
#define SEQ   2048
#define EMB   1024
#define NH    16
#define HD    64
#define MROWS (BATCH*SEQ)   // 4096
#define ACT_N (MROWS*EMB)
#define W_N   (EMB*EMB)

// ---------------------------------------------------------------------------
// Scratch (__device__ globals; no runtime allocation)
// ---------------------------------------------------------------------------
__device__ __half g_a1[3*ACT_N];                  // activations single fp16
__device__ __half g_wh[4*W_N];                    // weights^T single fp16
__device__ __half g_qh[ACT_N];                    // Q post-RoPE single
__device__ __half g_kh[ACT_N];                    // K post-RoPE single
__device__ __half g_vth[ACT_N];                   // V^T [b,h,d,s] single
__device__ __half g_oh[ACT_N];                    // attention out single
__device__ float2 g_rope[SEQ*32];

// exp(s*0.125) == exp2(s * 0.125*log2(e))
#define EXPSCALE 0.18033688011112042f

// ---------------------------------------------------------------------------
// helpers
// ---------------------------------------------------------------------------
__device__ __forceinline__ uint32_t smem_u32(const void* p) {
    uint32_t a;
    asm("{ .reg .u64 t; cvta.to.shared.u64 t, %1; cvt.u32.u64 %0, t; }" : "=r"(a) : "l"(p));
    return a;
}
__device__ __forceinline__ void cpa16(uint32_t dst, const void* src) {
    asm volatile("cp.async.cg.shared.global [%0], [%1], 16;" :: "r"(dst), "l"(src));
}
#define CP_COMMIT() asm volatile("cp.async.commit_group;" ::: "memory")
#define CP_WAIT1()  asm volatile("cp.async.wait_group 1;" ::: "memory")

__device__ __forceinline__ void mma4(float* c, const uint32_t* a, uint32_t b0, uint32_t b1) {
    asm volatile(
        "mma.sync.aligned.m16n8k16.row.col.f32.f16.f16.f32 "
        "{%0,%1,%2,%3}, {%4,%5,%6,%7}, {%8,%9}, {%0,%1,%2,%3};"
        : "+f"(c[0]), "+f"(c[1]), "+f"(c[2]), "+f"(c[3])
        : "r"(a[0]), "r"(a[1]), "r"(a[2]), "r"(a[3]), "r"(b0), "r"(b1));
}
__device__ __forceinline__ void ldsm4(uint32_t* r, uint32_t a) {
    asm volatile("ldmatrix.sync.aligned.m8n8.x4.shared.b16 {%0,%1,%2,%3}, [%4];"
        : "=r"(r[0]), "=r"(r[1]), "=r"(r[2]), "=r"(r[3]) : "r"(a));
}

// 128B-row swizzle (8 chunks of 16B, xor by row&7) — conflict-free ldmatrix
#define SW128X(row, ch) ((row) * 128 + (((ch) ^ (row)) & 7) * 16)

// ---------------------------------------------------------------------------
// RoPE table
// ---------------------------------------------------------------------------
__global__ void rope_table_kernel(float2* __restrict__ tab) {
    int i = blockIdx.x * 256 + threadIdx.x;
    if (i >= SEQ * 32) return;
    int p = i & 31, s = i >> 5;
    double inv = pow(10000.0, -(double)p * (1.0 / 32.0));
    float ph = (float)((double)s * inv);
    float sn, cs;
    sincosf(ph, &sn, &cs);
    tab[i] = make_float2(cs, sn);
}

// ---------------------------------------------------------------------------
// merged input conversions: fp32 -> single fp16, z = 0,1,2 (query,key,value)
// ---------------------------------------------------------------------------
__global__ void __launch_bounds__(256) conv3(const float* __restrict__ x0,
                                             const float* __restrict__ x1,
                                             const float* __restrict__ x2,
                                             __half* __restrict__ hi) {
    int z = blockIdx.y;
    const float* x = (z == 0) ? x0 : (z == 1) ? x1 : x2;
    size_t i = ((size_t)blockIdx.x * 256 + threadIdx.x) * 4;
    float4 v = *(const float4*)(x + i);
    size_t o = (size_t)z * ACT_N + i;
    *(__half2*)(hi + o)     = __halves2half2(__float2half_rn(v.x), __float2half_rn(v.y));
    *(__half2*)(hi + o + 2) = __halves2half2(__float2half_rn(v.z), __float2half_rn(v.w));
}

// merged W[K,N] fp32 -> Wt[N,K] single fp16, z = 0..3 (Wq,Wk,Wv,Wo)
__global__ void __launch_bounds__(256) convT4(const float* __restrict__ W0,
                                              const float* __restrict__ W1,
                                              const float* __restrict__ W2,
                                              const float* __restrict__ W3,
                                              __half* __restrict__ hi) {
    __shared__ float t[32][33];
    int z = blockIdx.z;
    const float* W = (z == 0) ? W0 : (z == 1) ? W1 : (z == 2) ? W2 : W3;
    int tx = threadIdx.x & 31;
    int ty = threadIdx.x >> 5;
    int bk = blockIdx.y * 32, bn = blockIdx.x * 32;
#pragma unroll
    for (int r = ty; r < 32; r += 8)
        t[r][tx] = W[(size_t)(bk + r) * EMB + bn + tx];
    __syncthreads();
#pragma unroll
    for (int r = ty; r < 32; r += 8) {
        size_t o = (size_t)z * W_N + (size_t)(bn + r) * EMB + bk + tx;
        hi[o] = __float2half_rn(t[tx][r]);
    }
}

// ---------------------------------------------------------------------------
// Projection GEMM: BM=128 BN=128 BK=64; 8 warps (4m x 2n), ldmatrix,
// single-pass fp16. 3-stage cp.async, 16 k-iters, hoisted addresses.
// (R14 configuration — occ 2, 127 regs; occ-3 regressed via spills)
// epi: 0 = RoPE + single store (Q/K); 1 = transposed single store (V^T);
//      2 = fp32 store (output projection)
// ---------------------------------------------------------------------------
#define PJ_STAGE 32768
#define PJ_SMEM  (3*PJ_STAGE)   // 98304
#define PJ_ITERS 16

__device__ __forceinline__ void gemm_core(
    const __half* __restrict__ Ah, const __half* __restrict__ Bh,
    __half* __restrict__ Ch, float* __restrict__ Cf,
    const float2* __restrict__ rope, int epi, char* sm)
{
    const uint32_t sb = smem_u32(sm);
    const int tid  = threadIdx.x;
    const int lane = tid & 31;
    const int wid  = tid >> 5;
    const int g    = lane >> 2;
    const int c    = lane & 3;
    const int quad = lane >> 3;
    const int lr   = lane & 7;
    const int m0 = blockIdx.y * 128;
    const int n0 = blockIdx.x * 128;
    const int wm = (wid & 3) * 32;
    const int wn = (wid >> 2) * 64;

    const int a_row = (quad & 1) * 8 + lr;
    const int a_chi = quad >> 1;
    const int b_row = (quad >> 1) * 8 + lr;
    const int b_chi = quad & 1;

    // hoisted staging addresses: t=0..3 -> A rows, t=4..7 -> B rows
    const __half* Abase = Ah + (size_t)m0 * EMB;
    const __half* Bbase = Bh + (size_t)n0 * EMB;
    uint32_t soff[8], goff[8];
#pragma unroll
    for (int t = 0; t < 8; t++) {
        int idx = t * 256 + tid;
        int buf = idx >> 10;           // 0:A 1:B
        int rem = idx & 1023;
        int row = rem >> 3;
        int j   = rem & 7;
        soff[t] = buf * 16384 + SW128X(row, j);
        goff[t] = row * EMB + j * 8;
    }

    float acc[2][8][4];
#pragma unroll
    for (int i = 0; i < 2; i++)
#pragma unroll
        for (int j = 0; j < 8; j++)
#pragma unroll
            for (int q = 0; q < 4; q++) acc[i][j][q] = 0.f;

    auto stage = [&](int kt, int s) {
        uint32_t base = sb + s * PJ_STAGE;
        uint32_t kadd = kt * 64;
#pragma unroll
        for (int t = 0; t < 4; t++)
            cpa16(base + soff[t], Abase + goff[t] + kadd);
#pragma unroll
        for (int t = 4; t < 8; t++)
            cpa16(base + soff[t], Bbase + goff[t] + kadd);
    };

    stage(0, 0); CP_COMMIT();
    stage(1, 1); CP_COMMIT();

#pragma unroll 1
    for (int kt = 0; kt < PJ_ITERS; kt++) {
        const int s = kt - (kt / 3) * 3;
        CP_WAIT1();
        __syncthreads();
        if (kt + 2 < PJ_ITERS) {
            int s2 = (kt + 2) - ((kt + 2) / 3) * 3;
            stage(kt + 2, s2);
        }
        CP_COMMIT();

        const uint32_t base = sb + s * PJ_STAGE;
#pragma unroll
        for (int kk = 0; kk < 4; kk++) {
            uint32_t aH[2][4];
#pragma unroll
            for (int mf = 0; mf < 2; mf++) {
                int row = wm + mf * 16 + a_row;
                int ch  = kk * 2 + a_chi;
                ldsm4(aH[mf], base + SW128X(row, ch));
            }
#pragma unroll
            for (int ngp = 0; ngp < 2; ngp++) {
                int ch = kk * 2 + b_chi;
                uint32_t bv0[4], bv1[4];
                ldsm4(bv0, base + 16384 + SW128X(wn + (ngp * 2 + 0) * 16 + b_row, ch));
                ldsm4(bv1, base + 16384 + SW128X(wn + (ngp * 2 + 1) * 16 + b_row, ch));
#pragma unroll
                for (int t = 0; t < 2; t++)
#pragma unroll
                    for (int mf = 0; mf < 2; mf++) {
                        mma4(acc[mf][(ngp * 2 + 0) * 2 + t], aH[mf], bv0[t * 2], bv0[t * 2 + 1]);
                        mma4(acc[mf][(ngp * 2 + 1) * 2 + t], aH[mf], bv1[t * 2], bv1[t * 2 + 1]);
                    }
            }
        }
    }

    // ---- epilogue ----
#pragma unroll
    for (int mf = 0; mf < 2; mf++) {
#pragma unroll
        for (int rr = 0; rr < 2; rr++) {
            int row = m0 + wm + mf * 16 + g + rr * 8;
            if (epi == 0) {
                int ss = row & (SEQ - 1);
#pragma unroll
                for (int ns = 0; ns < 4; ns++) {
                    int p = ns * 8 + 2 * c;
                    float2 r0 = rope[ss * 32 + p];
                    float2 r1 = rope[ss * 32 + p + 1];
                    float x00 = acc[mf][ns][rr * 2 + 0],     x01 = acc[mf][ns][rr * 2 + 1];
                    float x10 = acc[mf][ns + 4][rr * 2 + 0], x11 = acc[mf][ns + 4][rr * 2 + 1];
                    float o00 = x00 * r0.x - x10 * r0.y;
                    float o10 = x10 * r0.x + x00 * r0.y;
                    float o01 = x01 * r1.x - x11 * r1.y;
                    float o11 = x11 * r1.x + x01 * r1.y;
                    size_t col = (size_t)row * EMB + n0 + wn + p;
                    *(__half2*)(Ch + col) =
                        __halves2half2(__float2half_rn(o00), __float2half_rn(o01));
                    *(__half2*)(Ch + col + 32) =
                        __halves2half2(__float2half_rn(o10), __float2half_rn(o11));
                }
            } else if (epi == 1) {
                int bq = row >> 11;
                int sq = row & (SEQ - 1);
#pragma unroll
                for (int ns = 0; ns < 8; ns++) {
                    int col = n0 + wn + ns * 8 + 2 * c;
                    int hh = col >> 6, d = col & 63;
                    size_t dst = ((size_t)(bq * NH + hh) * 64 + d) * SEQ + sq;
                    Ch[dst]       = __float2half_rn(acc[mf][ns][rr * 2]);
                    Ch[dst + SEQ] = __float2half_rn(acc[mf][ns][rr * 2 + 1]);
                }
            } else {
#pragma unroll
                for (int ns = 0; ns < 8; ns++) {
                    size_t col = (size_t)row * EMB + n0 + wn + ns * 8 + 2 * c;
                    *(float2*)(Cf + col) =
                        make_float2(acc[mf][ns][rr * 2], acc[mf][ns][rr * 2 + 1]);
                }
            }
        }
    }
}

__global__ void __launch_bounds__(256, 2)
gemm_qkv(const __half* __restrict__ a1, const __half* __restrict__ wh,
         __half* __restrict__ qh, __half* __restrict__ kh,
         __half* __restrict__ vth, const float2* __restrict__ rope)
{
    extern __shared__ char sm[];
    int z = blockIdx.z;
    const __half* Ah = a1 + (size_t)z * ACT_N;
    const __half* Bh = wh + (size_t)z * W_N;
    __half* Ch = (z == 0) ? qh : (z == 1) ? kh : vth;
    gemm_core(Ah, Bh, Ch, nullptr, rope, (z < 2) ? 0 : 1, sm);
}

__global__ void __launch_bounds__(256, 2)
gemm_one(const __half* __restrict__ Ah, const __half* __restrict__ Bh,
         float* __restrict__ Cf)
{
    extern __shared__ char sm[];
    gemm_core(Ah, Bh, nullptr, Cf, nullptr, 2, sm);
}

// ---------------------------------------------------------------------------
// Flash attention: all-fp16 single-pass MMAs; fp16x2 MUFU softmax;
// Q fragments hoisted into registers once (reused across all 32 chunks);
// hoisted staging addresses; 3 KV stages.
// smem: Q 0..16K; KV stage s at 16384 + s*16384 (K +0, V +8192)
// ---------------------------------------------------------------------------
#define AT_KV 16384
#define AT_STAGE 16384
#define AT_SMEM (16384 + 3*16384)   // 65536

__global__ void __launch_bounds__(256, 2)
attn_kernel(const __half* __restrict__ Qh, const __half* __restrict__ Kh,
            const __half* __restrict__ Vth, __half* __restrict__ Oh)
{
    extern __shared__ char sm[];
    const uint32_t sb = smem_u32(sm);
    const int tid  = threadIdx.x;
    const int lane = tid & 31;
    const int wid  = tid >> 5;
    const int g    = lane >> 2;
    const int c    = lane & 3;
    const int quad = lane >> 3;
    const int lr   = lane & 7;
    const int q0 = blockIdx.x * 128;
    const int h  = blockIdx.y;
    const int b  = blockIdx.z;
    const int bh = b * NH + h;

    const int a_row = (quad & 1) * 8 + lr;
    const int a_chi = quad >> 1;
    const int b_row = (quad >> 1) * 8 + lr;
    const int b_chi = quad & 1;

    __half2 e2h = __half2half2(__float2half_rn(EXPSCALE));
    const uint32_t esc2 = *(uint32_t*)&e2h;

    // hoisted KV staging addresses: t=0,1 -> K rows, t=2,3 -> V rows
    uint32_t soffKV[4], goffKV[4];
#pragma unroll
    for (int t = 0; t < 4; t++) {
        int idx = t * 256 + tid;
        int buf = idx >> 9;            // 0:K 1:V
        int rem = idx & 511;
        int row = rem >> 3;
        int j   = rem & 7;
        soffKV[t] = buf * 8192 + SW128X(row, j);
        goffKV[t] = buf ? ((uint32_t)(bh * 64 + row) * SEQ + j * 8)
                        : ((uint32_t)(b * SEQ + row) * EMB + h * 64 + j * 8);
    }

    auto stage_kv = [&](int kt, int s) {
        uint32_t base = sb + AT_KV + s * AT_STAGE;
        uint32_t kaddK = (uint32_t)kt * EMB;
        cpa16(base + soffKV[0], Kh  + goffKV[0] + kaddK);
        cpa16(base + soffKV[1], Kh  + goffKV[1] + kaddK);
        cpa16(base + soffKV[2], Vth + goffKV[2] + kt);
        cpa16(base + soffKV[3], Vth + goffKV[3] + kt);
    };

    // stage Q (once) + chunks 0,1
#pragma unroll
    for (int t = 0; t < 4; t++) {
        int idx = t * 256 + tid;
        int row = idx >> 3;
        int j   = idx & 7;
        cpa16(sb + SW128X(row, j),
              Qh + (size_t)(b * SEQ + q0 + row) * EMB + h * 64 + j * 8);
    }
    stage_kv(0, 0);
    CP_COMMIT();
    stage_kv(64, 1);
    CP_COMMIT();

    float Of[8][4];
#pragma unroll
    for (int n = 0; n < 8; n++)
#pragma unroll
        for (int q = 0; q < 4; q++) Of[n][q] = 0.f;
    float lA = 0.f, lB = 0.f;

    uint32_t qf[4][4];   // Q fragments, loaded once at ic==0

#pragma unroll 1
    for (int ic = 0; ic < SEQ / 64; ic++) {
        const int s = ic - (ic / 3) * 3;
        CP_WAIT1();
        __syncthreads();
        if (ic + 2 < SEQ / 64) {
            int s2 = (ic + 2) - ((ic + 2) / 3) * 3;
            stage_kv((ic + 2) * 64, s2);
        }
        CP_COMMIT();

        if (ic == 0) {
            // Q visible now (group with chunk 0 drained); load frags once
#pragma unroll
            for (int kk = 0; kk < 4; kk++) {
                int row = wid * 16 + a_row;
                int ch  = kk * 2 + a_chi;
                ldsm4(qf[kk], sb + SW128X(row, ch));
            }
        }

        const uint32_t kvb = sb + AT_KV + s * AT_STAGE;

        // ---- S = Q K^T (single pass, Q frags in registers) ----
        float Sf[8][4];
#pragma unroll
        for (int n = 0; n < 8; n++)
#pragma unroll
            for (int q = 0; q < 4; q++) Sf[n][q] = 0.f;

#pragma unroll
        for (int kk = 0; kk < 4; kk++) {
#pragma unroll
            for (int ngp = 0; ngp < 2; ngp++) {
                int ch = kk * 2 + b_chi;
                uint32_t bv0[4], bv1[4];
                ldsm4(bv0, kvb + 0 + SW128X((ngp * 2 + 0) * 16 + b_row, ch));
                ldsm4(bv1, kvb + 0 + SW128X((ngp * 2 + 1) * 16 + b_row, ch));
                mma4(Sf[ngp * 4 + 0], qf[kk], bv0[0], bv0[1]);
                mma4(Sf[ngp * 4 + 1], qf[kk], bv0[2], bv0[3]);
                mma4(Sf[ngp * 4 + 2], qf[kk], bv1[0], bv1[1]);
                mma4(Sf[ngp * 4 + 3], qf[kk], bv1[2], bv1[3]);
            }
        }

        // ---- softmax in fp16x2: P = ex2(s * scale) ----
        uint32_t P01[8], P23[8];
        uint32_t sumA2 = 0, sumB2 = 0;
#pragma unroll
        for (int ns = 0; ns < 8; ns++) {
            uint32_t a01, a23;
            asm("cvt.rn.f16x2.f32 %0, %1, %2;" : "=r"(a01) : "f"(Sf[ns][1]), "f"(Sf[ns][0]));
            asm("cvt.rn.f16x2.f32 %0, %1, %2;" : "=r"(a23) : "f"(Sf[ns][3]), "f"(Sf[ns][2]));
            asm("mul.rn.f16x2 %0, %0, %1;" : "+r"(a01) : "r"(esc2));
            asm("mul.rn.f16x2 %0, %0, %1;" : "+r"(a23) : "r"(esc2));
            asm("ex2.approx.f16x2 %0, %0;" : "+r"(a01));
            asm("ex2.approx.f16x2 %0, %0;" : "+r"(a23));
            P01[ns] = a01;
            P23[ns] = a23;
            asm("add.rn.f16x2 %0, %0, %1;" : "+r"(sumA2) : "r"(a01));
            asm("add.rn.f16x2 %0, %0, %1;" : "+r"(sumB2) : "r"(a23));
        }
        {
            float2 fa = __half22float2(*(__half2*)&sumA2);
            float2 fb = __half22float2(*(__half2*)&sumB2);
            lA += fa.x + fa.y;
            lB += fb.x + fb.y;
        }

        // ---- O += P V ----
#pragma unroll
        for (int kk = 0; kk < 4; kk++) {
            uint32_t ah2[4] = {P01[2 * kk], P23[2 * kk], P01[2 * kk + 1], P23[2 * kk + 1]};
#pragma unroll
            for (int ngp = 0; ngp < 2; ngp++) {
                int ch = kk * 2 + b_chi;
                uint32_t vv0[4], vv1[4];
                ldsm4(vv0, kvb + 8192 + SW128X((ngp * 2 + 0) * 16 + b_row, ch));
                ldsm4(vv1, kvb + 8192 + SW128X((ngp * 2 + 1) * 16 + b_row, ch));
                mma4(Of[ngp * 4 + 0], ah2, vv0[0], vv0[1]);
                mma4(Of[ngp * 4 + 1], ah2, vv0[2], vv0[3]);
                mma4(Of[ngp * 4 + 2], ah2, vv1[0], vv1[1]);
                mma4(Of[ngp * 4 + 3], ah2, vv1[2], vv1[3]);
            }
        }
    }

    // ---- epilogue: single cross-lane reduce, normalize, single fp16 store ----
    lA += __shfl_xor_sync(0xffffffffu, lA, 1);
    lA += __shfl_xor_sync(0xffffffffu, lA, 2);
    lB += __shfl_xor_sync(0xffffffffu, lB, 1);
    lB += __shfl_xor_sync(0xffffffffu, lB, 2);
    float iA = 1.0f / lA, iB = 1.0f / lB;
#pragma unroll
    for (int rr = 0; rr < 2; rr++) {
        int row = b * SEQ + q0 + wid * 16 + g + rr * 8;
        float sc = rr ? iB : iA;
#pragma unroll
        for (int nf = 0; nf < 8; nf++) {
            size_t col = (size_t)row * EMB + h * 64 + nf * 8 + 2 * c;
            *(__half2*)(Oh + col) =
                __halves2half2(__float2half_rn(Of[nf][rr * 2] * sc),
                               __float2half_rn(Of[nf][rr * 2 + 1] * sc));
        }
    }
}

// ---------------------------------------------------------------------------
extern "C" void kernel_launch(void* const* d_in, const int* in_sizes, int n_in,
                              void* d_out, int out_size)
{
    const float* query = (const float*)d_in[0];
    const float* key   = (const float*)d_in[1];
    const float* value = (const float*)d_in[2];
    const float* Wq    = (const float*)d_in[3];
    const float* Wk    = (const float*)d_in[4];
    const float* Wv    = (const float*)d_in[5];
    const float* Wo    = (const float*)d_in[6];
    float* out = (float*)d_out;

    __half *a1, *wh, *qh, *kh, *vth, *oh;
    float2* rope;
    cudaGetSymbolAddress((void**)&a1, g_a1);
    cudaGetSymbolAddress((void**)&wh, g_wh);
    cudaGetSymbolAddress((void**)&qh, g_qh);
    cudaGetSymbolAddress((void**)&kh, g_kh);
    cudaGetSymbolAddress((void**)&vth, g_vth);
    cudaGetSymbolAddress((void**)&oh, g_oh);
    cudaGetSymbolAddress((void**)&rope, g_rope);

    cudaFuncSetAttribute(gemm_qkv,    cudaFuncAttributeMaxDynamicSharedMemorySize, PJ_SMEM);
    cudaFuncSetAttribute(gemm_one,    cudaFuncAttributeMaxDynamicSharedMemorySize, PJ_SMEM);
    cudaFuncSetAttribute(attn_kernel, cudaFuncAttributeMaxDynamicSharedMemorySize, AT_SMEM);

    rope_table_kernel<<<SEQ * 32 / 256, 256>>>(rope);

    conv3<<<dim3(ACT_N / 1024, 3), 256>>>(query, key, value, a1);
    convT4<<<dim3(32, 32, 4), 256>>>(Wq, Wk, Wv, Wo, wh);

    gemm_qkv<<<dim3(EMB / 128, MROWS / 128, 3), 256, PJ_SMEM>>>(
        a1, wh, qh, kh, vth, rope);

    attn_kernel<<<dim3(SEQ / 128, NH, BATCH), 256, AT_SMEM>>>(
        qh, kh, vth, oh);

    gemm_one<<<dim3(EMB / 128, MROWS / 128), 256, PJ_SMEM>>>(
        oh, wh + (size_t)3 * W_N, out);
}

// round 17
// speedup vs baseline: 1.3727x; 1.0088x over previous
#include <cuda_runtime.h>
#include <cuda_fp16.h>
#include <math.h>
#include <stdint.h>

#define BATCH 2
#define SEQ   2048
#define EMB   1024
#define NH    16
#define HD    64
#define MROWS (BATCH*SEQ)   // 4096
#define ACT_N (MROWS*EMB)
#define W_N   (EMB*EMB)

// ---------------------------------------------------------------------------
// Scratch (__device__ globals; no runtime allocation)
// ---------------------------------------------------------------------------
__device__ __half g_a1[3*ACT_N];                  // activations single fp16
__device__ __half g_wh[4*W_N];                    // weights^T single fp16
__device__ __half g_qh[ACT_N];                    // Q post-RoPE single
__device__ __half g_kh[ACT_N];                    // K post-RoPE single
__device__ __half g_vth[ACT_N];                   // V^T [b,h,d,s] single
__device__ __half g_oh[ACT_N];                    // attention out single
__device__ float2 g_rope[SEQ*32];

// exp(s*0.125) == exp2(s * 0.125*log2(e))
#define EXPSCALE 0.18033688011112042f

// ---------------------------------------------------------------------------
// helpers
// ---------------------------------------------------------------------------
__device__ __forceinline__ uint32_t smem_u32(const void* p) {
    uint32_t a;
    asm("{ .reg .u64 t; cvta.to.shared.u64 t, %1; cvt.u32.u64 %0, t; }" : "=r"(a) : "l"(p));
    return a;
}
__device__ __forceinline__ void cpa16(uint32_t dst, const void* src) {
    asm volatile("cp.async.cg.shared.global [%0], [%1], 16;" :: "r"(dst), "l"(src));
}
#define CP_COMMIT() asm volatile("cp.async.commit_group;" ::: "memory")
#define CP_WAIT0()  asm volatile("cp.async.wait_group 0;" ::: "memory")
#define CP_WAIT1()  asm volatile("cp.async.wait_group 1;" ::: "memory")

__device__ __forceinline__ void mma4(float* c, const uint32_t* a, uint32_t b0, uint32_t b1) {
    asm volatile(
        "mma.sync.aligned.m16n8k16.row.col.f32.f16.f16.f32 "
        "{%0,%1,%2,%3}, {%4,%5,%6,%7}, {%8,%9}, {%0,%1,%2,%3};"
        : "+f"(c[0]), "+f"(c[1]), "+f"(c[2]), "+f"(c[3])
        : "r"(a[0]), "r"(a[1]), "r"(a[2]), "r"(a[3]), "r"(b0), "r"(b1));
}
__device__ __forceinline__ void ldsm4(uint32_t* r, uint32_t a) {
    asm volatile("ldmatrix.sync.aligned.m8n8.x4.shared.b16 {%0,%1,%2,%3}, [%4];"
        : "=r"(r[0]), "=r"(r[1]), "=r"(r[2]), "=r"(r[3]) : "r"(a));
}

// 128B-row swizzle (8 chunks of 16B, xor by row&7) — conflict-free ldmatrix
#define SW128X(row, ch) ((row) * 128 + (((ch) ^ (row)) & 7) * 16)

// ---------------------------------------------------------------------------
// RoPE table
// ---------------------------------------------------------------------------
__global__ void rope_table_kernel(float2* __restrict__ tab) {
    int i = blockIdx.x * 256 + threadIdx.x;
    if (i >= SEQ * 32) return;
    int p = i & 31, s = i >> 5;
    double inv = pow(10000.0, -(double)p * (1.0 / 32.0));
    float ph = (float)((double)s * inv);
    float sn, cs;
    sincosf(ph, &sn, &cs);
    tab[i] = make_float2(cs, sn);
}

// ---------------------------------------------------------------------------
// merged input conversions: fp32 -> single fp16, z = 0,1,2 (query,key,value)
// ---------------------------------------------------------------------------
__global__ void __launch_bounds__(256) conv3(const float* __restrict__ x0,
                                             const float* __restrict__ x1,
                                             const float* __restrict__ x2,
                                             __half* __restrict__ hi) {
    int z = blockIdx.y;
    const float* x = (z == 0) ? x0 : (z == 1) ? x1 : x2;
    size_t i = ((size_t)blockIdx.x * 256 + threadIdx.x) * 4;
    float4 v = *(const float4*)(x + i);
    size_t o = (size_t)z * ACT_N + i;
    *(__half2*)(hi + o)     = __halves2half2(__float2half_rn(v.x), __float2half_rn(v.y));
    *(__half2*)(hi + o + 2) = __halves2half2(__float2half_rn(v.z), __float2half_rn(v.w));
}

// merged W[K,N] fp32 -> Wt[N,K] single fp16, z = 0..3 (Wq,Wk,Wv,Wo)
__global__ void __launch_bounds__(256) convT4(const float* __restrict__ W0,
                                              const float* __restrict__ W1,
                                              const float* __restrict__ W2,
                                              const float* __restrict__ W3,
                                              __half* __restrict__ hi) {
    __shared__ float t[32][33];
    int z = blockIdx.z;
    const float* W = (z == 0) ? W0 : (z == 1) ? W1 : (z == 2) ? W2 : W3;
    int tx = threadIdx.x & 31;
    int ty = threadIdx.x >> 5;
    int bk = blockIdx.y * 32, bn = blockIdx.x * 32;
#pragma unroll
    for (int r = ty; r < 32; r += 8)
        t[r][tx] = W[(size_t)(bk + r) * EMB + bn + tx];
    __syncthreads();
#pragma unroll
    for (int r = ty; r < 32; r += 8) {
        size_t o = (size_t)z * W_N + (size_t)(bn + r) * EMB + bk + tx;
        hi[o] = __float2half_rn(t[tx][r]);
    }
}

// ---------------------------------------------------------------------------
// Projection GEMM: BM=128 BN=128 BK=64; 8 warps (4m x 2n), ldmatrix,
// single-pass fp16. 3-stage cp.async, 16 k-iters, hoisted addresses.
// (R14/R16 configuration — occ 2, 127 regs; proven floor)
// epi: 0 = RoPE + single store (Q/K); 1 = transposed single store (V^T);
//      2 = fp32 store (output projection)
// ---------------------------------------------------------------------------
#define PJ_STAGE 32768
#define PJ_SMEM  (3*PJ_STAGE)   // 98304
#define PJ_ITERS 16

__device__ __forceinline__ void gemm_core(
    const __half* __restrict__ Ah, const __half* __restrict__ Bh,
    __half* __restrict__ Ch, float* __restrict__ Cf,
    const float2* __restrict__ rope, int epi, char* sm)
{
    const uint32_t sb = smem_u32(sm);
    const int tid  = threadIdx.x;
    const int lane = tid & 31;
    const int wid  = tid >> 5;
    const int g    = lane >> 2;
    const int c    = lane & 3;
    const int quad = lane >> 3;
    const int lr   = lane & 7;
    const int m0 = blockIdx.y * 128;
    const int n0 = blockIdx.x * 128;
    const int wm = (wid & 3) * 32;
    const int wn = (wid >> 2) * 64;

    const int a_row = (quad & 1) * 8 + lr;
    const int a_chi = quad >> 1;
    const int b_row = (quad >> 1) * 8 + lr;
    const int b_chi = quad & 1;

    // hoisted staging addresses: t=0..3 -> A rows, t=4..7 -> B rows
    const __half* Abase = Ah + (size_t)m0 * EMB;
    const __half* Bbase = Bh + (size_t)n0 * EMB;
    uint32_t soff[8], goff[8];
#pragma unroll
    for (int t = 0; t < 8; t++) {
        int idx = t * 256 + tid;
        int buf = idx >> 10;           // 0:A 1:B
        int rem = idx & 1023;
        int row = rem >> 3;
        int j   = rem & 7;
        soff[t] = buf * 16384 + SW128X(row, j);
        goff[t] = row * EMB + j * 8;
    }

    float acc[2][8][4];
#pragma unroll
    for (int i = 0; i < 2; i++)
#pragma unroll
        for (int j = 0; j < 8; j++)
#pragma unroll
            for (int q = 0; q < 4; q++) acc[i][j][q] = 0.f;

    auto stage = [&](int kt, int s) {
        uint32_t base = sb + s * PJ_STAGE;
        uint32_t kadd = kt * 64;
#pragma unroll
        for (int t = 0; t < 4; t++)
            cpa16(base + soff[t], Abase + goff[t] + kadd);
#pragma unroll
        for (int t = 4; t < 8; t++)
            cpa16(base + soff[t], Bbase + goff[t] + kadd);
    };

    stage(0, 0); CP_COMMIT();
    stage(1, 1); CP_COMMIT();

#pragma unroll 1
    for (int kt = 0; kt < PJ_ITERS; kt++) {
        const int s = kt - (kt / 3) * 3;
        CP_WAIT1();
        __syncthreads();
        if (kt + 2 < PJ_ITERS) {
            int s2 = (kt + 2) - ((kt + 2) / 3) * 3;
            stage(kt + 2, s2);
        }
        CP_COMMIT();

        const uint32_t base = sb + s * PJ_STAGE;
#pragma unroll
        for (int kk = 0; kk < 4; kk++) {
            uint32_t aH[2][4];
#pragma unroll
            for (int mf = 0; mf < 2; mf++) {
                int row = wm + mf * 16 + a_row;
                int ch  = kk * 2 + a_chi;
                ldsm4(aH[mf], base + SW128X(row, ch));
            }
#pragma unroll
            for (int ngp = 0; ngp < 2; ngp++) {
                int ch = kk * 2 + b_chi;
                uint32_t bv0[4], bv1[4];
                ldsm4(bv0, base + 16384 + SW128X(wn + (ngp * 2 + 0) * 16 + b_row, ch));
                ldsm4(bv1, base + 16384 + SW128X(wn + (ngp * 2 + 1) * 16 + b_row, ch));
#pragma unroll
                for (int t = 0; t < 2; t++)
#pragma unroll
                    for (int mf = 0; mf < 2; mf++) {
                        mma4(acc[mf][(ngp * 2 + 0) * 2 + t], aH[mf], bv0[t * 2], bv0[t * 2 + 1]);
                        mma4(acc[mf][(ngp * 2 + 1) * 2 + t], aH[mf], bv1[t * 2], bv1[t * 2 + 1]);
                    }
            }
        }
    }

    // ---- epilogue ----
#pragma unroll
    for (int mf = 0; mf < 2; mf++) {
#pragma unroll
        for (int rr = 0; rr < 2; rr++) {
            int row = m0 + wm + mf * 16 + g + rr * 8;
            if (epi == 0) {
                int ss = row & (SEQ - 1);
#pragma unroll
                for (int ns = 0; ns < 4; ns++) {
                    int p = ns * 8 + 2 * c;
                    float2 r0 = rope[ss * 32 + p];
                    float2 r1 = rope[ss * 32 + p + 1];
                    float x00 = acc[mf][ns][rr * 2 + 0],     x01 = acc[mf][ns][rr * 2 + 1];
                    float x10 = acc[mf][ns + 4][rr * 2 + 0], x11 = acc[mf][ns + 4][rr * 2 + 1];
                    float o00 = x00 * r0.x - x10 * r0.y;
                    float o10 = x10 * r0.x + x00 * r0.y;
                    float o01 = x01 * r1.x - x11 * r1.y;
                    float o11 = x11 * r1.x + x01 * r1.y;
                    size_t col = (size_t)row * EMB + n0 + wn + p;
                    *(__half2*)(Ch + col) =
                        __halves2half2(__float2half_rn(o00), __float2half_rn(o01));
                    *(__half2*)(Ch + col + 32) =
                        __halves2half2(__float2half_rn(o10), __float2half_rn(o11));
                }
            } else if (epi == 1) {
                int bq = row >> 11;
                int sq = row & (SEQ - 1);
#pragma unroll
                for (int ns = 0; ns < 8; ns++) {
                    int col = n0 + wn + ns * 8 + 2 * c;
                    int hh = col >> 6, d = col & 63;
                    size_t dst = ((size_t)(bq * NH + hh) * 64 + d) * SEQ + sq;
                    Ch[dst]       = __float2half_rn(acc[mf][ns][rr * 2]);
                    Ch[dst + SEQ] = __float2half_rn(acc[mf][ns][rr * 2 + 1]);
                }
            } else {
#pragma unroll
                for (int ns = 0; ns < 8; ns++) {
                    size_t col = (size_t)row * EMB + n0 + wn + ns * 8 + 2 * c;
                    *(float2*)(Cf + col) =
                        make_float2(acc[mf][ns][rr * 2], acc[mf][ns][rr * 2 + 1]);
                }
            }
        }
    }
}

__global__ void __launch_bounds__(256, 2)
gemm_qkv(const __half* __restrict__ a1, const __half* __restrict__ wh,
         __half* __restrict__ qh, __half* __restrict__ kh,
         __half* __restrict__ vth, const float2* __restrict__ rope)
{
    extern __shared__ char sm[];
    int z = blockIdx.z;
    const __half* Ah = a1 + (size_t)z * ACT_N;
    const __half* Bh = wh + (size_t)z * W_N;
    __half* Ch = (z == 0) ? qh : (z == 1) ? kh : vth;
    gemm_core(Ah, Bh, Ch, nullptr, rope, (z < 2) ? 0 : 1, sm);
}

__global__ void __launch_bounds__(256, 2)
gemm_one(const __half* __restrict__ Ah, const __half* __restrict__ Bh,
         float* __restrict__ Cf)
{
    extern __shared__ char sm[];
    gemm_core(Ah, Bh, nullptr, Cf, nullptr, 2, sm);
}

// ---------------------------------------------------------------------------
// Flash attention: all-fp16 single-pass MMAs; fp16x2 MUFU softmax;
// Q frags hoisted into registers; 4 KV stages, ONE wait+sync+commit per
// chunk PAIR (halves barrier count vs per-chunk pipeline).
// smem: Q 0..16K; KV stage s at 16384 + s*16384 (K +0, V +8192)
// ---------------------------------------------------------------------------
#define AT_KV 16384
#define AT_STAGE 16384
#define AT_SMEM (16384 + 4*16384)   // 81920

__global__ void __launch_bounds__(256, 2)
attn_kernel(const __half* __restrict__ Qh, const __half* __restrict__ Kh,
            const __half* __restrict__ Vth, __half* __restrict__ Oh)
{
    extern __shared__ char sm[];
    const uint32_t sb = smem_u32(sm);
    const int tid  = threadIdx.x;
    const int lane = tid & 31;
    const int wid  = tid >> 5;
    const int g    = lane >> 2;
    const int c    = lane & 3;
    const int quad = lane >> 3;
    const int lr   = lane & 7;
    const int q0 = blockIdx.x * 128;
    const int h  = blockIdx.y;
    const int b  = blockIdx.z;
    const int bh = b * NH + h;

    const int a_row = (quad & 1) * 8 + lr;
    const int a_chi = quad >> 1;
    const int b_row = (quad >> 1) * 8 + lr;
    const int b_chi = quad & 1;

    __half2 e2h = __half2half2(__float2half_rn(EXPSCALE));
    const uint32_t esc2 = *(uint32_t*)&e2h;

    // hoisted KV staging addresses: t=0,1 -> K rows, t=2,3 -> V rows
    uint32_t soffKV[4], goffKV[4];
#pragma unroll
    for (int t = 0; t < 4; t++) {
        int idx = t * 256 + tid;
        int buf = idx >> 9;            // 0:K 1:V
        int rem = idx & 511;
        int row = rem >> 3;
        int j   = rem & 7;
        soffKV[t] = buf * 8192 + SW128X(row, j);
        goffKV[t] = buf ? ((uint32_t)(bh * 64 + row) * SEQ + j * 8)
                        : ((uint32_t)(b * SEQ + row) * EMB + h * 64 + j * 8);
    }

    auto stage_kv = [&](int kt, int s) {
        uint32_t base = sb + AT_KV + s * AT_STAGE;
        uint32_t kaddK = (uint32_t)kt * EMB;
        cpa16(base + soffKV[0], Kh  + goffKV[0] + kaddK);
        cpa16(base + soffKV[1], Kh  + goffKV[1] + kaddK);
        cpa16(base + soffKV[2], Vth + goffKV[2] + kt);
        cpa16(base + soffKV[3], Vth + goffKV[3] + kt);
    };

    // prologue: Q + chunks 0,1 (group 1), chunks 2,3 (group 2)
#pragma unroll
    for (int t = 0; t < 4; t++) {
        int idx = t * 256 + tid;
        int row = idx >> 3;
        int j   = idx & 7;
        cpa16(sb + SW128X(row, j),
              Qh + (size_t)(b * SEQ + q0 + row) * EMB + h * 64 + j * 8);
    }
    stage_kv(0, 0);
    stage_kv(64, 1);
    CP_COMMIT();
    stage_kv(128, 2);
    stage_kv(192, 3);
    CP_COMMIT();

    float Of[8][4];
#pragma unroll
    for (int n = 0; n < 8; n++)
#pragma unroll
        for (int q = 0; q < 4; q++) Of[n][q] = 0.f;
    float lA = 0.f, lB = 0.f;

    uint32_t qf[4][4];   // Q fragments, loaded once at p==0

    // per-chunk compute body
    auto do_chunk = [&](int stg) {
        const uint32_t kvb = sb + AT_KV + stg * AT_STAGE;

        // ---- S = Q K^T ----
        float Sf[8][4];
#pragma unroll
        for (int n = 0; n < 8; n++)
#pragma unroll
            for (int q = 0; q < 4; q++) Sf[n][q] = 0.f;

#pragma unroll
        for (int kk = 0; kk < 4; kk++) {
#pragma unroll
            for (int ngp = 0; ngp < 2; ngp++) {
                int ch = kk * 2 + b_chi;
                uint32_t bv0[4], bv1[4];
                ldsm4(bv0, kvb + 0 + SW128X((ngp * 2 + 0) * 16 + b_row, ch));
                ldsm4(bv1, kvb + 0 + SW128X((ngp * 2 + 1) * 16 + b_row, ch));
                mma4(Sf[ngp * 4 + 0], qf[kk], bv0[0], bv0[1]);
                mma4(Sf[ngp * 4 + 1], qf[kk], bv0[2], bv0[3]);
                mma4(Sf[ngp * 4 + 2], qf[kk], bv1[0], bv1[1]);
                mma4(Sf[ngp * 4 + 3], qf[kk], bv1[2], bv1[3]);
            }
        }

        // ---- softmax in fp16x2 ----
        uint32_t P01[8], P23[8];
        uint32_t sumA2 = 0, sumB2 = 0;
#pragma unroll
        for (int ns = 0; ns < 8; ns++) {
            uint32_t a01, a23;
            asm("cvt.rn.f16x2.f32 %0, %1, %2;" : "=r"(a01) : "f"(Sf[ns][1]), "f"(Sf[ns][0]));
            asm("cvt.rn.f16x2.f32 %0, %1, %2;" : "=r"(a23) : "f"(Sf[ns][3]), "f"(Sf[ns][2]));
            asm("mul.rn.f16x2 %0, %0, %1;" : "+r"(a01) : "r"(esc2));
            asm("mul.rn.f16x2 %0, %0, %1;" : "+r"(a23) : "r"(esc2));
            asm("ex2.approx.f16x2 %0, %0;" : "+r"(a01));
            asm("ex2.approx.f16x2 %0, %0;" : "+r"(a23));
            P01[ns] = a01;
            P23[ns] = a23;
            asm("add.rn.f16x2 %0, %0, %1;" : "+r"(sumA2) : "r"(a01));
            asm("add.rn.f16x2 %0, %0, %1;" : "+r"(sumB2) : "r"(a23));
        }
        {
            float2 fa = __half22float2(*(__half2*)&sumA2);
            float2 fb = __half22float2(*(__half2*)&sumB2);
            lA += fa.x + fa.y;
            lB += fb.x + fb.y;
        }

        // ---- O += P V ----
#pragma unroll
        for (int kk = 0; kk < 4; kk++) {
            uint32_t ah2[4] = {P01[2 * kk], P23[2 * kk], P01[2 * kk + 1], P23[2 * kk + 1]};
#pragma unroll
            for (int ngp = 0; ngp < 2; ngp++) {
                int ch = kk * 2 + b_chi;
                uint32_t vv0[4], vv1[4];
                ldsm4(vv0, kvb + 8192 + SW128X((ngp * 2 + 0) * 16 + b_row, ch));
                ldsm4(vv1, kvb + 8192 + SW128X((ngp * 2 + 1) * 16 + b_row, ch));
                mma4(Of[ngp * 4 + 0], ah2, vv0[0], vv0[1]);
                mma4(Of[ngp * 4 + 1], ah2, vv0[2], vv0[3]);
                mma4(Of[ngp * 4 + 2], ah2, vv1[0], vv1[1]);
                mma4(Of[ngp * 4 + 3], ah2, vv1[2], vv1[3]);
            }
        }
    };

#pragma unroll 1
    for (int p = 0; p < SEQ / 64; p += 2) {
        CP_WAIT0();                    // chunks p, p+1 (and everything earlier) landed
        __syncthreads();               // all warps past reading chunks p-2, p-1
        if (p == 0) {
            // Q visible now; load frags once
#pragma unroll
            for (int kk = 0; kk < 4; kk++) {
                int row = wid * 16 + a_row;
                int ch  = kk * 2 + a_chi;
                ldsm4(qf[kk], sb + SW128X(row, ch));
            }
        }
        if (p + 2 < SEQ / 64) {
            stage_kv((p + 2) * 64, (p + 2) & 3);   // overwrites stage of p-2 (safe)
            stage_kv((p + 3) * 64, (p + 3) & 3);   // overwrites stage of p-1 (safe)
            CP_COMMIT();
        }
        do_chunk(p & 3);
        do_chunk((p + 1) & 3);
    }

    // ---- epilogue: single cross-lane reduce, normalize, single fp16 store ----
    lA += __shfl_xor_sync(0xffffffffu, lA, 1);
    lA += __shfl_xor_sync(0xffffffffu, lA, 2);
    lB += __shfl_xor_sync(0xffffffffu, lB, 1);
    lB += __shfl_xor_sync(0xffffffffu, lB, 2);
    float iA = 1.0f / lA, iB = 1.0f / lB;
#pragma unroll
    for (int rr = 0; rr < 2; rr++) {
        int row = b * SEQ + q0 + wid * 16 + g + rr * 8;
        float sc = rr ? iB : iA;
#pragma unroll
        for (int nf = 0; nf < 8; nf++) {
            size_t col = (size_t)row * EMB + h * 64 + nf * 8 + 2 * c;
            *(__half2*)(Oh + col) =
                __halves2half2(__float2half_rn(Of[nf][rr * 2] * sc),
                               __float2half_rn(Of[nf][rr * 2 + 1] * sc));
        }
    }
}

// ---------------------------------------------------------------------------
extern "C" void kernel_launch(void* const* d_in, const int* in_sizes, int n_in,
                              void* d_out, int out_size)
{
    const float* query = (const float*)d_in[0];
    const float* key   = (const float*)d_in[1];
    const float* value = (const float*)d_in[2];
    const float* Wq    = (const float*)d_in[3];
    const float* Wk    = (const float*)d_in[4];
    const float* Wv    = (const float*)d_in[5];
    const float* Wo    = (const float*)d_in[6];
    float* out = (float*)d_out;

    __half *a1, *wh, *qh, *kh, *vth, *oh;
    float2* rope;
    cudaGetSymbolAddress((void**)&a1, g_a1);
    cudaGetSymbolAddress((void**)&wh, g_wh);
    cudaGetSymbolAddress((void**)&qh, g_qh);
    cudaGetSymbolAddress((void**)&kh, g_kh);
    cudaGetSymbolAddress((void**)&vth, g_vth);
    cudaGetSymbolAddress((void**)&oh, g_oh);
    cudaGetSymbolAddress((void**)&rope, g_rope);

    cudaFuncSetAttribute(gemm_qkv,    cudaFuncAttributeMaxDynamicSharedMemorySize, PJ_SMEM);
    cudaFuncSetAttribute(gemm_one,    cudaFuncAttributeMaxDynamicSharedMemorySize, PJ_SMEM);
    cudaFuncSetAttribute(attn_kernel, cudaFuncAttributeMaxDynamicSharedMemorySize, AT_SMEM);

    rope_table_kernel<<<SEQ * 32 / 256, 256>>>(rope);

    conv3<<<dim3(ACT_N / 1024, 3), 256>>>(query, key, value, a1);
    convT4<<<dim3(32, 32, 4), 256>>>(Wq, Wk, Wv, Wo, wh);

    gemm_qkv<<<dim3(EMB / 128, MROWS / 128, 3), 256, PJ_SMEM>>>(
        a1, wh, qh, kh, vth, rope);

    attn_kernel<<<dim3(SEQ / 128, NH, BATCH), 256, AT_SMEM>>>(
        qh, kh, vth, oh);

    gemm_one<<<dim3(EMB / 128, MROWS / 128), 256, PJ_SMEM>>>(
        oh, wh + (size_t)3 * W_N, out);
}